// round 1
// baseline (speedup 1.0000x reference)
#include <cuda_runtime.h>

// ---------------------------------------------------------------------------
// EnsembleCausalPredictor: E=4, F=16, O=9, B=512, DIN=32, DH=128, H=4, DK=32
// Pipeline: fc1 -> fc2 -> 2x ChannelMHA (qkv, attn, wo+res, post_fc) -> pool
//           -> predictor fc -> final [B,17]
// All GEMMs are batched over 576 (=E*F*O) or 64 (=E*F) channels.
// ---------------------------------------------------------------------------

#define NE 4
#define NF 16
#define NO 9
#define NB 512
#define NDIN 32
#define NDH 128
#define NFINAL 17
#define NEF (NE*NF)        // 64
#define NCH (NEF*NO)       // 576

// Scratch (static device globals; allocation-free per harness rules).
#define HBUF (NCH*NB*NDH)  // 37,748,736 floats
__device__ float g_h1[HBUF];
__device__ float g_h2[HBUF];
__device__ float g_q [HBUF];
__device__ float g_k [HBUF];
__device__ float g_v [HBUF];
__device__ float g_t [HBUF];
__device__ float g_po[NEF*NB*NDH];  // pooled
__device__ float g_p [NEF*NB*NDH];  // predictor hidden

// ---------------------------------------------------------------------------
// Batched SGEMM: C[batch,512,128] = A[batch,512,K] @ W[batch,K,128]
//   (+bias[batch,128]) (+Res[batch,512,128]) (relu)
// Block: 256 threads, 128x128 output tile, BK=16, 8x8 per-thread microtile.
// Grid: (512/128, batch).
// ---------------------------------------------------------------------------
template<int K, bool RELU, bool BIAS, bool RES>
__global__ void __launch_bounds__(256) gemm_bn(
    const float* __restrict__ A,
    const float* __restrict__ W,
    const float* __restrict__ bias,
    const float* __restrict__ Res,
    float* __restrict__ C)
{
    const int mt = blockIdx.x;
    const int bz = blockIdx.y;
    const float* Ab = A + (size_t)bz * 512 * K + (size_t)mt * 128 * K;
    const float* Wb = W + (size_t)bz * K * 128;
    float*       Cb = C + (size_t)bz * 512 * 128 + (size_t)mt * 128 * 128;
    const float* Rb = RES ? (Res + (size_t)bz * 512 * 128 + (size_t)mt * 128 * 128)
                          : nullptr;

    __shared__ float As[16][132];   // transposed A tile (k-major), padded
    __shared__ float Ws[16][128];   // W tile (k-major rows)

    const int t  = threadIdx.x;
    const int tx = t & 15;          // column group (8 cols each)
    const int ty = t >> 4;          // row group (8 rows each)

    float acc[8][8];
    #pragma unroll
    for (int i = 0; i < 8; i++)
        #pragma unroll
        for (int j = 0; j < 8; j++) acc[i][j] = 0.f;

    for (int k0 = 0; k0 < K; k0 += 16) {
        // A tile: 128 rows x 16 k; 2 threads per row, float4 x2 each.
        {
            int r = t >> 1;
            int c = (t & 1) * 8;
            const float* src = Ab + (size_t)r * K + k0 + c;
            float4 v0 = *(const float4*)(src);
            float4 v1 = *(const float4*)(src + 4);
            As[c + 0][r] = v0.x; As[c + 1][r] = v0.y;
            As[c + 2][r] = v0.z; As[c + 3][r] = v0.w;
            As[c + 4][r] = v1.x; As[c + 5][r] = v1.y;
            As[c + 6][r] = v1.z; As[c + 7][r] = v1.w;
        }
        // W tile: 16 rows x 128 cols, contiguous -> 512 float4s.
        {
            const float4* src = (const float4*)(Wb + (size_t)k0 * 128);
            float4* dst = (float4*)(&Ws[0][0]);
            dst[t]       = src[t];
            dst[t + 256] = src[t + 256];
        }
        __syncthreads();
        #pragma unroll
        for (int k = 0; k < 16; k++) {
            float a[8], w[8];
            *(float4*)(a)     = *(const float4*)&As[k][ty * 8];
            *(float4*)(a + 4) = *(const float4*)&As[k][ty * 8 + 4];
            *(float4*)(w)     = *(const float4*)&Ws[k][tx * 8];
            *(float4*)(w + 4) = *(const float4*)&Ws[k][tx * 8 + 4];
            #pragma unroll
            for (int i = 0; i < 8; i++)
                #pragma unroll
                for (int j = 0; j < 8; j++)
                    acc[i][j] += a[i] * w[j];
        }
        __syncthreads();
    }

    float bcol[8];
    if (BIAS) {
        #pragma unroll
        for (int j = 0; j < 8; j++)
            bcol[j] = bias[(size_t)bz * 128 + tx * 8 + j];
    }
    #pragma unroll
    for (int i = 0; i < 8; i++) {
        int row = ty * 8 + i;
        float* cp = Cb + (size_t)row * 128 + tx * 8;
        float4 r0, r1;
        if (RES) {
            r0 = *(const float4*)(Rb + (size_t)row * 128 + tx * 8);
            r1 = *(const float4*)(Rb + (size_t)row * 128 + tx * 8 + 4);
        }
        float rr[8];
        if (RES) { rr[0]=r0.x; rr[1]=r0.y; rr[2]=r0.z; rr[3]=r0.w;
                   rr[4]=r1.x; rr[5]=r1.y; rr[6]=r1.z; rr[7]=r1.w; }
        float o[8];
        #pragma unroll
        for (int j = 0; j < 8; j++) {
            float v = acc[i][j];
            if (BIAS) v += bcol[j];
            if (RES)  v += rr[j];
            if (RELU) v = fmaxf(v, 0.f);
            o[j] = v;
        }
        *(float4*)(cp)     = make_float4(o[0], o[1], o[2], o[3]);
        *(float4*)(cp + 4) = make_float4(o[4], o[5], o[6], o[7]);
    }
}

// ---------------------------------------------------------------------------
// Attention core. One block per (ef, b): stage q,k,v [9][128] in smem,
// compute 4x9x9 logits, softmax over last axis, out = attn @ v.
// ---------------------------------------------------------------------------
__global__ void __launch_bounds__(128) attn_kernel(
    const float* __restrict__ Q, const float* __restrict__ Kk,
    const float* __restrict__ V, float* __restrict__ T)
{
    const int blk = blockIdx.x;       // ef*512 + b
    const int ef  = blk >> 9;
    const int b   = blk & 511;

    __shared__ float qs[NO][132];
    __shared__ float ks[NO][132];
    __shared__ float vs[NO][132];
    __shared__ float lg[4][NO][12];

    const int t = threadIdx.x;

    for (int idx = t; idx < NO * 128; idx += 128) {
        int o = idx >> 7;
        int c = idx & 127;
        size_t g = ((size_t)(ef * NO + o) * NB + b) * 128 + c;
        qs[o][c] = Q[g];
        ks[o][c] = Kk[g];
        vs[o][c] = V[g];
    }
    __syncthreads();

    const float scale = 0.17677669529663687f;  // 1/sqrt(32)
    for (int e = t; e < 4 * NO * NO; e += 128) {
        int h   = e / (NO * NO);
        int rem = e - h * NO * NO;
        int i   = rem / NO;
        int j   = rem - i * NO;
        float s = 0.f;
        #pragma unroll
        for (int d = 0; d < 32; d++)
            s += qs[i][h * 32 + d] * ks[j][h * 32 + d];
        lg[h][i][j] = s * scale;
    }
    __syncthreads();

    if (t < 4 * NO) {
        int h = t / NO, i = t - h * NO;
        float m = -1e30f;
        #pragma unroll
        for (int j = 0; j < NO; j++) m = fmaxf(m, lg[h][i][j]);
        float ex[NO];
        float s = 0.f;
        #pragma unroll
        for (int j = 0; j < NO; j++) { ex[j] = __expf(lg[h][i][j] - m); s += ex[j]; }
        float inv = 1.f / s;
        #pragma unroll
        for (int j = 0; j < NO; j++) lg[h][i][j] = ex[j] * inv;
    }
    __syncthreads();

    const int c = t;           // channel 0..127
    const int h = c >> 5;
    #pragma unroll
    for (int i = 0; i < NO; i++) {
        float s = 0.f;
        #pragma unroll
        for (int j = 0; j < NO; j++) s += lg[h][i][j] * vs[j][c];
        T[((size_t)(ef * NO + i) * NB + b) * 128 + c] = s;
    }
}

// ---------------------------------------------------------------------------
// Mean over object axis: P[ef,b,c] = mean_o H[ef,o,b,c]
// ---------------------------------------------------------------------------
__global__ void __launch_bounds__(256) pool_kernel(
    const float* __restrict__ Hin, float* __restrict__ P)
{
    int idx = blockIdx.x * 256 + threadIdx.x;
    if (idx >= NEF * NB * NDH) return;
    int c  = idx & 127;
    int b  = (idx >> 7) & 511;
    int ef = idx >> 16;
    float s = 0.f;
    #pragma unroll
    for (int o = 0; o < NO; o++)
        s += Hin[((size_t)(ef * NO + o) * NB + b) * 128 + c];
    P[idx] = s * (1.f / 9.f);
}

// ---------------------------------------------------------------------------
// Final projection: Out[ef,b,0:17] = P[ef,b,:] @ pw2[ef,:,:] + pb2[ef,:]
// Block handles (ef, 32-row tile).
// ---------------------------------------------------------------------------
__global__ void __launch_bounds__(256) final_kernel(
    const float* __restrict__ A,    // [64,512,128]
    const float* __restrict__ W,    // [64,128,17]
    const float* __restrict__ bias, // [64,17]
    float* __restrict__ Out)        // [64,512,17]
{
    const int mt = blockIdx.x;   // 0..15 (32 rows each)
    const int ef = blockIdx.y;

    __shared__ float As[32][128];
    __shared__ float Ws[128][NFINAL];
    __shared__ float bs[NFINAL];

    const int t = threadIdx.x;
    const float* Ab = A + ((size_t)ef * NB + mt * 32) * 128;

    for (int i = t; i < 32 * 128 / 4; i += 256)
        ((float4*)&As[0][0])[i] = ((const float4*)Ab)[i];
    for (int i = t; i < 128 * NFINAL; i += 256)
        Ws[i / NFINAL][i % NFINAL] = W[(size_t)ef * 128 * NFINAL + i];
    if (t < NFINAL) bs[t] = bias[ef * NFINAL + t];
    __syncthreads();

    for (int idx = t; idx < 32 * NFINAL; idx += 256) {
        int r = idx / NFINAL, j = idx - r * NFINAL;
        float s = bs[j];
        #pragma unroll 16
        for (int k = 0; k < 128; k++) s += As[r][k] * Ws[k][j];
        Out[((size_t)ef * NB + mt * 32 + r) * NFINAL + j] = s;
    }
}

// ---------------------------------------------------------------------------
extern "C" void kernel_launch(void* const* d_in, const int* in_sizes, int n_in,
                              void* d_out, int out_size)
{
    const float* x   = (const float*)d_in[0];
    const float* fw1 = (const float*)d_in[1];
    const float* fb1 = (const float*)d_in[2];
    const float* fw2 = (const float*)d_in[3];
    const float* fb2 = (const float*)d_in[4];
    const float* aw[2][5];
    const float* apb[2];
    for (int i = 0; i < 2; i++) {
        for (int n = 0; n < 5; n++) aw[i][n] = (const float*)d_in[5 + i * 6 + n];
        apb[i] = (const float*)d_in[5 + i * 6 + 5];
    }
    const float* pw1 = (const float*)d_in[17];
    const float* pb1 = (const float*)d_in[18];
    const float* pw2 = (const float*)d_in[19];
    const float* pb2 = (const float*)d_in[20];
    float* out = (float*)d_out;

    float *H1, *H2, *Q, *K, *V, *T, *PO, *P;
    cudaGetSymbolAddress((void**)&H1, g_h1);
    cudaGetSymbolAddress((void**)&H2, g_h2);
    cudaGetSymbolAddress((void**)&Q,  g_q);
    cudaGetSymbolAddress((void**)&K,  g_k);
    cudaGetSymbolAddress((void**)&V,  g_v);
    cudaGetSymbolAddress((void**)&T,  g_t);
    cudaGetSymbolAddress((void**)&PO, g_po);
    cudaGetSymbolAddress((void**)&P,  g_p);

    dim3 gg(4, NCH);    // 128-row tiles x 576 channels
    dim3 gp(4, NEF);    // predictor: 64 channels

    // feature_fc
    gemm_bn<32,  true, true, false><<<gg, 256>>>(x,  fw1, fb1, nullptr, H1);
    gemm_bn<128, true, true, false><<<gg, 256>>>(H1, fw2, fb2, nullptr, H2);

    // two ChannelMHA blocks
    const float* X = H2;
    float* Y = H1;
    for (int a = 0; a < 2; a++) {
        gemm_bn<128, false, false, false><<<gg, 256>>>(X, aw[a][0], nullptr, nullptr, Q);
        gemm_bn<128, false, false, false><<<gg, 256>>>(X, aw[a][1], nullptr, nullptr, K);
        gemm_bn<128, false, false, false><<<gg, 256>>>(X, aw[a][2], nullptr, nullptr, V);
        attn_kernel<<<NEF * NB, 128>>>(Q, K, V, T);
        // Q := T @ wo + X  (residual)
        gemm_bn<128, false, false, true><<<gg, 256>>>(T, aw[a][3], nullptr, X, Q);
        // Y := relu(Q @ pw + pb)
        gemm_bn<128, true, true, false><<<gg, 256>>>(Q, aw[a][4], apb[a], nullptr, Y);
        const float* nX = Y;
        Y = (a == 0) ? H2 : H1;
        X = nX;
    }
    // X now points at the final hidden state (H2 after a=1)

    pool_kernel<<<(NEF * NB * NDH + 255) / 256, 256>>>(X, PO);
    gemm_bn<128, true, true, false><<<gp, 256>>>(PO, pw1, pb1, nullptr, P);
    final_kernel<<<dim3(16, NEF), 256>>>(P, pw2, pb2, out);
}

// round 3
// speedup vs baseline: 1.2142x; 1.2142x over previous
#include <cuda_runtime.h>
#include <cuda_bf16.h>
#include <cstdint>

// ---------------------------------------------------------------------------
// EnsembleCausalPredictor: E=4, F=16, O=9, B=512, DIN=32, DH=128, H=4, DK=32
// GEMMs on tcgen05 (bf16 hi/lo split, fp32 TMEM accumulate) when the
// arch-specific (sm_103a) compilation pass is active; FFMA fallback otherwise.
// ---------------------------------------------------------------------------

#define NE 4
#define NF 16
#define NO 9
#define NB 512
#define NDH 128
#define NFINAL 17
#define NEF (NE*NF)        // 64
#define NCH (NEF*NO)       // 576

#define HBUF (NCH*NB*NDH)
__device__ float g_h1[HBUF];
__device__ float g_h2[HBUF];
__device__ float g_q [HBUF];
__device__ float g_k [HBUF];
__device__ float g_v [HBUF];
__device__ float g_t [HBUF];
__device__ float g_po[NEF*NB*NDH];
__device__ float g_p [NEF*NB*NDH];

// tcgen05 is an arch-SPECIFIC feature: only present in the sm_103a/sm_100a
// device pass. The family/base pass (sm_103) must not see the asm.
#if defined(__CUDA_ARCH_FEAT_SM103_ALL) || defined(__CUDA_ARCH_FEAT_SM100_ALL)
#define TC_OK 1
#else
#define TC_OK 0
#endif

// ------------------------------- PTX helpers ------------------------------
__device__ __forceinline__ uint32_t smem_u32(const void* p) {
    uint32_t a;
    asm("{ .reg .u64 tmp; cvta.to.shared.u64 tmp, %1; cvt.u32.u64 %0, tmp; }"
        : "=r"(a) : "l"(p));
    return a;
}

#if TC_OK
__device__ __forceinline__ uint32_t elect_one() {
    uint32_t p;
    asm volatile("{\n\t.reg .pred p;\n\telect.sync _|p, 0xFFFFFFFF;\n\t"
                 "selp.b32 %0, 1, 0, p;\n\t}" : "=r"(p));
    return p;
}
#define TC_ALLOC(sa, n) \
    asm volatile("tcgen05.alloc.cta_group::1.sync.aligned.shared::cta.b32 [%0], %1;" \
                 :: "r"(sa), "r"(n) : "memory")
#define TC_DEALLOC(tm, n) \
    asm volatile("tcgen05.dealloc.cta_group::1.sync.aligned.b32 %0, %1;" :: "r"(tm), "r"(n))
#define MBAR_INIT(a, c) \
    asm volatile("mbarrier.init.shared.b64 [%0], %1;" :: "r"(a), "r"(c) : "memory")
#define MBAR_INVAL(a) \
    asm volatile("mbarrier.inval.shared.b64 [%0];" :: "r"(a) : "memory")
#define TC_COMMIT(a) \
    asm volatile("tcgen05.commit.cta_group::1.mbarrier::arrive::one.shared::cluster.b64 [%0];" \
                 :: "r"(a) : "memory")
#define TC_WAIT_LD()  asm volatile("tcgen05.wait::ld.sync.aligned;" ::: "memory")
#define TC_FENCE_AFTER()  asm volatile("tcgen05.fence::after_thread_sync;" ::: "memory")
#define TC_FENCE_BEFORE() asm volatile("tcgen05.fence::before_thread_sync;" ::: "memory")

__device__ __forceinline__ void mbar_wait(uint32_t a, uint32_t parity) {
    asm volatile(
        "{\n\t.reg .pred P1;\n\t"
        "WAIT_LOOP_%=:\n\t"
        "mbarrier.try_wait.parity.acquire.cta.shared::cta.b64 P1, [%0], %1, 0x989680;\n\t"
        "@P1 bra.uni WAIT_DONE_%=;\n\t"
        "bra.uni WAIT_LOOP_%=;\n\t"
        "WAIT_DONE_%=:\n\t}"
        :: "r"(a), "r"(parity) : "memory");
}

#define TC_LD_X32(r, tm) \
    asm volatile("tcgen05.ld.sync.aligned.32x32b.x32.b32 " \
        "{%0,%1,%2,%3,%4,%5,%6,%7,%8,%9,%10,%11,%12,%13,%14,%15," \
        "%16,%17,%18,%19,%20,%21,%22,%23,%24,%25,%26,%27,%28,%29,%30,%31}, [%32];" \
        : "=r"((r)[0]),"=r"((r)[1]),"=r"((r)[2]),"=r"((r)[3]), \
          "=r"((r)[4]),"=r"((r)[5]),"=r"((r)[6]),"=r"((r)[7]), \
          "=r"((r)[8]),"=r"((r)[9]),"=r"((r)[10]),"=r"((r)[11]), \
          "=r"((r)[12]),"=r"((r)[13]),"=r"((r)[14]),"=r"((r)[15]), \
          "=r"((r)[16]),"=r"((r)[17]),"=r"((r)[18]),"=r"((r)[19]), \
          "=r"((r)[20]),"=r"((r)[21]),"=r"((r)[22]),"=r"((r)[23]), \
          "=r"((r)[24]),"=r"((r)[25]),"=r"((r)[26]),"=r"((r)[27]), \
          "=r"((r)[28]),"=r"((r)[29]),"=r"((r)[30]),"=r"((r)[31]) \
        : "r"(tm))

// SMEM descriptor: SW128, version=1, SBO=64, LBO=1 (K-major atom layout)
__device__ __forceinline__ uint64_t mk_desc(uint32_t base) {
    const uint64_t B =
        (uint64_t(2) << 61) | (uint64_t(1) << 46) | (uint64_t(64) << 32) | (uint64_t(1) << 16);
    return B | ((uint64_t)(base >> 4) & 0x3FFF);
}

// cg1 kind::f16 SS MMA (bf16 in, fp32 acc)
__device__ __forceinline__ void mma_ss(uint32_t d, uint64_t a, uint64_t b,
                                       uint32_t idesc, uint32_t acc) {
    asm volatile(
        "{\n\t.reg .pred p;\n\tsetp.ne.u32 p, %4, 0;\n\t"
        "tcgen05.mma.cta_group::1.kind::f16 [%0], %1, %2, %3, {%5,%5,%5,%5}, p;\n\t}"
        :: "r"(d), "l"(a), "l"(b), "r"(idesc), "r"(acc), "r"(0u) : "memory");
}
#endif  // TC_OK

// idesc: dtype=F32(1<<4), atype=BF16(1<<7), btype=BF16(1<<10), N/8<<17, M/16<<24
#define IDESC_128 ((1u<<4)|(1u<<7)|(1u<<10)|((128u/8)<<17)|((128u/16)<<24))

// Blocked SW128 atom layout for a [128 rows, K cols] bf16 tile.
__device__ __forceinline__ uint32_t lay128(int r, int c) {
    uint32_t off = ((uint32_t)(c >> 6) * 16u + (uint32_t)(r >> 3)) * 1024u
                 + (uint32_t)(r & 7) * 128u + (uint32_t)(c & 63) * 2u;
    return off ^ ((off >> 3) & 0x70u);
}
// descriptor offset (16-byte units) for K-step s (16 bf16 per step)
__device__ __forceinline__ uint32_t doff(int s) {
    return (uint32_t)(s >> 2) * 1024u + (uint32_t)(s & 3) * 2u;
}

__device__ __forceinline__ uint32_t pack_bf2(float a, float b) {
    __nv_bfloat16 ha = __float2bfloat16_rn(a);
    __nv_bfloat16 hb = __float2bfloat16_rn(b);
    uint16_t ua = *(uint16_t*)&ha, ub = *(uint16_t*)&hb;
    return (uint32_t)ua | ((uint32_t)ub << 16);
}

// ---------------------------------------------------------------------------
// Batched GEMM: C[bz, 512, 128] = A[bz, 512, K] @ W[bz, K, 128]
//   (+bias) (+residual) (relu). Tile: M=128 x N=128 x K. 256 threads.
// ---------------------------------------------------------------------------
template<int K, bool RELU, bool BIAS, bool RES>
__global__ void __launch_bounds__(256) gemm_tc(
    const float* __restrict__ A,
    const float* __restrict__ W,
    const float* __restrict__ bias,
    const float* __restrict__ Res,
    float* __restrict__ C)
{
    extern __shared__ char smem[];
    const int t = threadIdx.x;
    const int mt = blockIdx.x, bz = blockIdx.y;

    const float* Ab = A + (size_t)bz * 512 * K + (size_t)mt * 128 * K;
    const float* Wb = W + (size_t)bz * K * 128;
    float*       Cb = C + ((size_t)bz * 512 + (size_t)mt * 128) * 128;
    const float* Rb = RES ? Res + ((size_t)bz * 512 + (size_t)mt * 128) * 128 : nullptr;

#if TC_OK
    // ======================= tcgen05 path (sm_103a) =======================
    constexpr int TILE = 128 * ((K >= 128) ? 256 : 128);  // bytes per bf16 tile
    constexpr int OFF_AH = 1024;
    constexpr int OFF_AL = OFF_AH + TILE;
    constexpr int OFF_WH = OFF_AL + TILE;
    constexpr int OFF_WL = OFF_WH + TILE;

    const uint32_t sb = smem_u32(smem);
    const int wid = t >> 5, lid = t & 31;
    float* bias_s = (float*)(smem + 256);

    if (wid == 0) TC_ALLOC(sb, 128);
    if (t == 0)   MBAR_INIT(sb + 8, 1);
    __syncthreads();
    uint32_t tmem;
    asm volatile("ld.shared.b32 %0, [%1];" : "=r"(tmem) : "r"(sb));

    // ---- convert A: fp32 [128,K] -> bf16 hi/lo, K-major blocked SW128 ----
    #pragma unroll
    for (int i = t; i < 128 * K / 4; i += 256) {
        int m  = i / (K / 4);
        int k4 = (i % (K / 4)) * 4;
        float4 v = *(const float4*)(Ab + (size_t)m * K + k4);
        float h0 = __bfloat162float(__float2bfloat16_rn(v.x));
        float h1 = __bfloat162float(__float2bfloat16_rn(v.y));
        float h2 = __bfloat162float(__float2bfloat16_rn(v.z));
        float h3 = __bfloat162float(__float2bfloat16_rn(v.w));
        uint2 hi = make_uint2(pack_bf2(v.x, v.y), pack_bf2(v.z, v.w));
        uint2 lo = make_uint2(pack_bf2(v.x - h0, v.y - h1), pack_bf2(v.z - h2, v.w - h3));
        uint32_t off = lay128(m, k4);
        *(uint2*)(smem + OFF_AH + off) = hi;
        *(uint2*)(smem + OFF_AL + off) = lo;
    }
    // ---- convert+transpose W: fp32 [K,128] -> bf16 hi/lo [N=128, K] ----
    #pragma unroll
    for (int i = t; i < (K / 2) * 32; i += 256) {
        int kp = i / 32;
        int n4 = (i % 32) * 4;
        float4 v0 = *(const float4*)(Wb + (size_t)(2 * kp) * 128 + n4);
        float4 v1 = *(const float4*)(Wb + (size_t)(2 * kp + 1) * 128 + n4);
        const float* e0 = (const float*)&v0;
        const float* e1 = (const float*)&v1;
        #pragma unroll
        for (int j = 0; j < 4; j++) {
            float x0 = e0[j], x1 = e1[j];
            float h0 = __bfloat162float(__float2bfloat16_rn(x0));
            float h1 = __bfloat162float(__float2bfloat16_rn(x1));
            uint32_t off = lay128(n4 + j, 2 * kp);
            *(uint32_t*)(smem + OFF_WH + off) = pack_bf2(x0, x1);
            *(uint32_t*)(smem + OFF_WL + off) = pack_bf2(x0 - h0, x1 - h1);
        }
    }
    if (BIAS && t < 128) bias_s[t] = bias[(size_t)bz * 128 + t];
    __syncthreads();

    // ---- MMA: D = Ah*Wh + Ah*Wl + Al*Wh (fp32 TMEM accumulate) ----
    if (wid == 0) {
        asm volatile("fence.proxy.async.shared::cta;" ::: "memory");
        if (elect_one()) {
            uint64_t ah = mk_desc(sb + OFF_AH);
            uint64_t al = mk_desc(sb + OFF_AL);
            uint64_t wh = mk_desc(sb + OFF_WH);
            uint64_t wl = mk_desc(sb + OFF_WL);
            constexpr int NS = K / 16;
            #pragma unroll
            for (int s = 0; s < NS; s++)
                mma_ss(tmem, ah + doff(s), wh + doff(s), IDESC_128, s > 0);
            #pragma unroll
            for (int s = 0; s < NS; s++)
                mma_ss(tmem, ah + doff(s), wl + doff(s), IDESC_128, 1);
            #pragma unroll
            for (int s = 0; s < NS; s++)
                mma_ss(tmem, al + doff(s), wh + doff(s), IDESC_128, 1);
            TC_COMMIT(sb + 8);
        }
    }
    mbar_wait(sb + 8, 0);
    TC_FENCE_AFTER();

    // ---- epilogue: 8 warps = 4 subpartitions x 2 column halves ----
    {
        const int sp = wid & 3;
        const int ch = wid >> 2;
        const int m  = sp * 32 + lid;
        float* cp = Cb + (size_t)m * 128;
        const float* rp = RES ? (Rb + (size_t)m * 128) : nullptr;
        #pragma unroll
        for (int cb = 0; cb < 2; cb++) {
            const int c0 = ch * 64 + cb * 32;
            uint32_t r[32];
            TC_LD_X32(r, tmem + c0);
            TC_WAIT_LD();
            #pragma unroll
            for (int q8 = 0; q8 < 8; q8++) {
                float4 v;
                v.x = __uint_as_float(r[q8 * 4 + 0]);
                v.y = __uint_as_float(r[q8 * 4 + 1]);
                v.z = __uint_as_float(r[q8 * 4 + 2]);
                v.w = __uint_as_float(r[q8 * 4 + 3]);
                if (BIAS) {
                    v.x += bias_s[c0 + q8 * 4 + 0];
                    v.y += bias_s[c0 + q8 * 4 + 1];
                    v.z += bias_s[c0 + q8 * 4 + 2];
                    v.w += bias_s[c0 + q8 * 4 + 3];
                }
                if (RES) {
                    float4 rv = *(const float4*)(rp + c0 + q8 * 4);
                    v.x += rv.x; v.y += rv.y; v.z += rv.z; v.w += rv.w;
                }
                if (RELU) {
                    v.x = fmaxf(v.x, 0.f); v.y = fmaxf(v.y, 0.f);
                    v.z = fmaxf(v.z, 0.f); v.w = fmaxf(v.w, 0.f);
                }
                *(float4*)(cp + c0 + q8 * 4) = v;
            }
        }
        TC_FENCE_BEFORE();
    }

    __syncthreads();
    if (t == 0) MBAR_INVAL(sb + 8);
    __syncthreads();
    if (wid == 0) TC_DEALLOC(tmem, 128);

#else
    // ================== FFMA fallback (base sm_103 pass) ==================
    float (*As)[132] = (float(*)[132])(smem + 1024);
    float (*Ws)[128] = (float(*)[128])(smem + 1024 + 16 * 132 * 4);

    const int tx = t & 15;
    const int ty = t >> 4;

    float acc[8][8];
    #pragma unroll
    for (int i = 0; i < 8; i++)
        #pragma unroll
        for (int j = 0; j < 8; j++) acc[i][j] = 0.f;

    for (int k0 = 0; k0 < K; k0 += 16) {
        {
            int r = t >> 1;
            int c = (t & 1) * 8;
            const float* src = Ab + (size_t)r * K + k0 + c;
            float4 v0 = *(const float4*)(src);
            float4 v1 = *(const float4*)(src + 4);
            As[c + 0][r] = v0.x; As[c + 1][r] = v0.y;
            As[c + 2][r] = v0.z; As[c + 3][r] = v0.w;
            As[c + 4][r] = v1.x; As[c + 5][r] = v1.y;
            As[c + 6][r] = v1.z; As[c + 7][r] = v1.w;
        }
        {
            const float4* src = (const float4*)(Wb + (size_t)k0 * 128);
            float4* dst = (float4*)(&Ws[0][0]);
            dst[t]       = src[t];
            dst[t + 256] = src[t + 256];
        }
        __syncthreads();
        #pragma unroll
        for (int k = 0; k < 16; k++) {
            float a[8], w[8];
            *(float4*)(a)     = *(const float4*)&As[k][ty * 8];
            *(float4*)(a + 4) = *(const float4*)&As[k][ty * 8 + 4];
            *(float4*)(w)     = *(const float4*)&Ws[k][tx * 8];
            *(float4*)(w + 4) = *(const float4*)&Ws[k][tx * 8 + 4];
            #pragma unroll
            for (int i = 0; i < 8; i++)
                #pragma unroll
                for (int j = 0; j < 8; j++)
                    acc[i][j] += a[i] * w[j];
        }
        __syncthreads();
    }

    float bcol[8];
    if (BIAS) {
        #pragma unroll
        for (int j = 0; j < 8; j++)
            bcol[j] = bias[(size_t)bz * 128 + tx * 8 + j];
    }
    #pragma unroll
    for (int i = 0; i < 8; i++) {
        int row = ty * 8 + i;
        float* cp = Cb + (size_t)row * 128 + tx * 8;
        float rr[8];
        if (RES) {
            float4 r0 = *(const float4*)(Rb + (size_t)row * 128 + tx * 8);
            float4 r1 = *(const float4*)(Rb + (size_t)row * 128 + tx * 8 + 4);
            rr[0]=r0.x; rr[1]=r0.y; rr[2]=r0.z; rr[3]=r0.w;
            rr[4]=r1.x; rr[5]=r1.y; rr[6]=r1.z; rr[7]=r1.w;
        }
        float o[8];
        #pragma unroll
        for (int j = 0; j < 8; j++) {
            float v = acc[i][j];
            if (BIAS) v += bcol[j];
            if (RES)  v += rr[j];
            if (RELU) v = fmaxf(v, 0.f);
            o[j] = v;
        }
        *(float4*)(cp)     = make_float4(o[0], o[1], o[2], o[3]);
        *(float4*)(cp + 4) = make_float4(o[4], o[5], o[6], o[7]);
    }
#endif
}

// ---------------------------------------------------------------------------
// Attention core: one block per (ef, b).
// ---------------------------------------------------------------------------
__global__ void __launch_bounds__(128) attn_kernel(
    const float* __restrict__ Q, const float* __restrict__ Kk,
    const float* __restrict__ V, float* __restrict__ T)
{
    const int blk = blockIdx.x;
    const int ef  = blk >> 9;
    const int b   = blk & 511;

    __shared__ float qs[NO][132];
    __shared__ float ks[NO][132];
    __shared__ float vs[NO][132];
    __shared__ float lg[4][NO][12];

    const int t = threadIdx.x;
    for (int idx = t; idx < NO * 128; idx += 128) {
        int o = idx >> 7, c = idx & 127;
        size_t g = ((size_t)(ef * NO + o) * NB + b) * 128 + c;
        qs[o][c] = Q[g]; ks[o][c] = Kk[g]; vs[o][c] = V[g];
    }
    __syncthreads();

    const float scale = 0.17677669529663687f;
    for (int e = t; e < 4 * NO * NO; e += 128) {
        int h = e / (NO * NO);
        int rem = e - h * NO * NO;
        int i = rem / NO, j = rem - (rem / NO) * NO;
        float s = 0.f;
        #pragma unroll
        for (int d = 0; d < 32; d++) s += qs[i][h * 32 + d] * ks[j][h * 32 + d];
        lg[h][i][j] = s * scale;
    }
    __syncthreads();

    if (t < 4 * NO) {
        int h = t / NO, i = t - (t / NO) * NO;
        float m = -1e30f;
        #pragma unroll
        for (int j = 0; j < NO; j++) m = fmaxf(m, lg[h][i][j]);
        float ex[NO]; float s = 0.f;
        #pragma unroll
        for (int j = 0; j < NO; j++) { ex[j] = __expf(lg[h][i][j] - m); s += ex[j]; }
        float inv = 1.f / s;
        #pragma unroll
        for (int j = 0; j < NO; j++) lg[h][i][j] = ex[j] * inv;
    }
    __syncthreads();

    const int c = t, h = c >> 5;
    #pragma unroll
    for (int i = 0; i < NO; i++) {
        float s = 0.f;
        #pragma unroll
        for (int j = 0; j < NO; j++) s += lg[h][i][j] * vs[j][c];
        T[((size_t)(ef * NO + i) * NB + b) * 128 + c] = s;
    }
}

__global__ void __launch_bounds__(256) pool_kernel(
    const float* __restrict__ Hin, float* __restrict__ P)
{
    int idx = blockIdx.x * 256 + threadIdx.x;
    if (idx >= NEF * NB * NDH) return;
    int c = idx & 127, b = (idx >> 7) & 511, ef = idx >> 16;
    float s = 0.f;
    #pragma unroll
    for (int o = 0; o < NO; o++)
        s += Hin[((size_t)(ef * NO + o) * NB + b) * 128 + c];
    P[idx] = s * (1.f / 9.f);
}

__global__ void __launch_bounds__(256) final_kernel(
    const float* __restrict__ A, const float* __restrict__ W,
    const float* __restrict__ bias, float* __restrict__ Out)
{
    const int mt = blockIdx.x;
    const int ef = blockIdx.y;
    __shared__ float As[32][128];
    __shared__ float Ws[128][NFINAL];
    __shared__ float bs[NFINAL];
    const int t = threadIdx.x;
    const float* Ab = A + ((size_t)ef * NB + mt * 32) * 128;
    for (int i = t; i < 32 * 128 / 4; i += 256)
        ((float4*)&As[0][0])[i] = ((const float4*)Ab)[i];
    for (int i = t; i < 128 * NFINAL; i += 256)
        Ws[i / NFINAL][i % NFINAL] = W[(size_t)ef * 128 * NFINAL + i];
    if (t < NFINAL) bs[t] = bias[ef * NFINAL + t];
    __syncthreads();
    for (int idx = t; idx < 32 * NFINAL; idx += 256) {
        int r = idx / NFINAL, j = idx - r * NFINAL;
        float s = bs[j];
        #pragma unroll 16
        for (int k = 0; k < 128; k++) s += As[r][k] * Ws[k][j];
        Out[((size_t)ef * NB + mt * 32 + r) * NFINAL + j] = s;
    }
}

// ---------------------------------------------------------------------------
extern "C" void kernel_launch(void* const* d_in, const int* in_sizes, int n_in,
                              void* d_out, int out_size)
{
    const float* x   = (const float*)d_in[0];
    const float* fw1 = (const float*)d_in[1];
    const float* fb1 = (const float*)d_in[2];
    const float* fw2 = (const float*)d_in[3];
    const float* fb2 = (const float*)d_in[4];
    const float* aw[2][5];
    const float* apb[2];
    for (int i = 0; i < 2; i++) {
        for (int n = 0; n < 5; n++) aw[i][n] = (const float*)d_in[5 + i * 6 + n];
        apb[i] = (const float*)d_in[5 + i * 6 + 5];
    }
    const float* pw1 = (const float*)d_in[17];
    const float* pb1 = (const float*)d_in[18];
    const float* pw2 = (const float*)d_in[19];
    const float* pb2 = (const float*)d_in[20];
    float* out = (float*)d_out;

    float *H1, *H2, *Q, *K, *V, *T, *PO, *P;
    cudaGetSymbolAddress((void**)&H1, g_h1);
    cudaGetSymbolAddress((void**)&H2, g_h2);
    cudaGetSymbolAddress((void**)&Q,  g_q);
    cudaGetSymbolAddress((void**)&K,  g_k);
    cudaGetSymbolAddress((void**)&V,  g_v);
    cudaGetSymbolAddress((void**)&T,  g_t);
    cudaGetSymbolAddress((void**)&PO, g_po);
    cudaGetSymbolAddress((void**)&P,  g_p);

    const int SM32  = 1024 + 4 * (128 * 128);   // 66,560
    const int SM128 = 1024 + 4 * (128 * 256);   // 132,096
    cudaFuncSetAttribute(gemm_tc<32,  true,  true,  false>,
                         cudaFuncAttributeMaxDynamicSharedMemorySize, SM32);
    cudaFuncSetAttribute(gemm_tc<128, true,  true,  false>,
                         cudaFuncAttributeMaxDynamicSharedMemorySize, SM128);
    cudaFuncSetAttribute(gemm_tc<128, false, false, false>,
                         cudaFuncAttributeMaxDynamicSharedMemorySize, SM128);
    cudaFuncSetAttribute(gemm_tc<128, false, false, true>,
                         cudaFuncAttributeMaxDynamicSharedMemorySize, SM128);

    dim3 gg(4, NCH);
    dim3 gp(4, NEF);

    // feature_fc
    gemm_tc<32,  true, true, false><<<gg, 256, SM32 >>>(x,  fw1, fb1, nullptr, H1);
    gemm_tc<128, true, true, false><<<gg, 256, SM128>>>(H1, fw2, fb2, nullptr, H2);

    // two ChannelMHA blocks
    const float* X = H2;
    float* Y = H1;
    for (int a = 0; a < 2; a++) {
        gemm_tc<128, false, false, false><<<gg, 256, SM128>>>(X, aw[a][0], nullptr, nullptr, Q);
        gemm_tc<128, false, false, false><<<gg, 256, SM128>>>(X, aw[a][1], nullptr, nullptr, K);
        gemm_tc<128, false, false, false><<<gg, 256, SM128>>>(X, aw[a][2], nullptr, nullptr, V);
        attn_kernel<<<NEF * NB, 128>>>(Q, K, V, T);
        gemm_tc<128, false, false, true ><<<gg, 256, SM128>>>(T, aw[a][3], nullptr, X, Q);
        gemm_tc<128, true,  true,  false><<<gg, 256, SM128>>>(Q, aw[a][4], apb[a], nullptr, Y);
        const float* nX = Y;
        Y = (a == 0) ? H2 : H1;
        X = nX;
    }

    pool_kernel<<<(NEF * NB * NDH + 255) / 256, 256>>>(X, PO);
    gemm_tc<128, true, true, false><<<gp, 256, SM128>>>(PO, pw1, pb1, nullptr, P);
    final_kernel<<<dim3(16, NEF), 256>>>(P, pw2, pb2, out);
}

// round 4
// speedup vs baseline: 1.6566x; 1.3643x over previous
#include <cuda_runtime.h>
#include <cuda_bf16.h>
#include <cstdint>

// ---------------------------------------------------------------------------
// EnsembleCausalPredictor: E=4, F=16, O=9, B=512, DIN=32, DH=128, H=4, DK=32
// Pipelined per-channel tcgen05 GEMM: W converted once per CTA, double-
// buffered A tiles, dual TMEM accumulators. bf16 hi/lo split, fp32 acc.
// ---------------------------------------------------------------------------

#define NE 4
#define NF 16
#define NO 9
#define NB 512
#define NDH 128
#define NFINAL 17
#define NEF (NE*NF)        // 64
#define NCH (NEF*NO)       // 576

#define HBUF (NCH*NB*NDH)
__device__ float g_h1[HBUF];
__device__ float g_h2[HBUF];
__device__ float g_q [HBUF];
__device__ float g_k [HBUF];
__device__ float g_v [HBUF];
__device__ float g_t [HBUF];
__device__ float g_po[NEF*NB*NDH];
__device__ float g_p [NEF*NB*NDH];

#if defined(__CUDA_ARCH_FEAT_SM103_ALL) || defined(__CUDA_ARCH_FEAT_SM100_ALL)
#define TC_OK 1
#else
#define TC_OK 0
#endif

// ------------------------------- PTX helpers ------------------------------
__device__ __forceinline__ uint32_t smem_u32(const void* p) {
    uint32_t a;
    asm("{ .reg .u64 tmp; cvta.to.shared.u64 tmp, %1; cvt.u32.u64 %0, tmp; }"
        : "=r"(a) : "l"(p));
    return a;
}

#if TC_OK
__device__ __forceinline__ uint32_t elect_one() {
    uint32_t p;
    asm volatile("{\n\t.reg .pred p;\n\telect.sync _|p, 0xFFFFFFFF;\n\t"
                 "selp.b32 %0, 1, 0, p;\n\t}" : "=r"(p));
    return p;
}
#define TC_ALLOC(sa, n) \
    asm volatile("tcgen05.alloc.cta_group::1.sync.aligned.shared::cta.b32 [%0], %1;" \
                 :: "r"(sa), "r"(n) : "memory")
#define TC_DEALLOC(tm, n) \
    asm volatile("tcgen05.dealloc.cta_group::1.sync.aligned.b32 %0, %1;" :: "r"(tm), "r"(n))
#define MBAR_INIT(a, c) \
    asm volatile("mbarrier.init.shared.b64 [%0], %1;" :: "r"(a), "r"(c) : "memory")
#define MBAR_INVAL(a) \
    asm volatile("mbarrier.inval.shared.b64 [%0];" :: "r"(a) : "memory")
#define TC_COMMIT(a) \
    asm volatile("tcgen05.commit.cta_group::1.mbarrier::arrive::one.shared::cluster.b64 [%0];" \
                 :: "r"(a) : "memory")
#define TC_WAIT_LD()  asm volatile("tcgen05.wait::ld.sync.aligned;" ::: "memory")
#define TC_FENCE_AFTER()  asm volatile("tcgen05.fence::after_thread_sync;" ::: "memory")
#define TC_FENCE_BEFORE() asm volatile("tcgen05.fence::before_thread_sync;" ::: "memory")
#define FENCE_ASYNC() asm volatile("fence.proxy.async.shared::cta;" ::: "memory")

__device__ __forceinline__ void mbar_wait(uint32_t a, uint32_t parity) {
    asm volatile(
        "{\n\t.reg .pred P1;\n\t"
        "WAIT_LOOP_%=:\n\t"
        "mbarrier.try_wait.parity.acquire.cta.shared::cta.b64 P1, [%0], %1, 0x989680;\n\t"
        "@P1 bra.uni WAIT_DONE_%=;\n\t"
        "bra.uni WAIT_LOOP_%=;\n\t"
        "WAIT_DONE_%=:\n\t}"
        :: "r"(a), "r"(parity) : "memory");
}

#define TC_LD_X32(r, tm) \
    asm volatile("tcgen05.ld.sync.aligned.32x32b.x32.b32 " \
        "{%0,%1,%2,%3,%4,%5,%6,%7,%8,%9,%10,%11,%12,%13,%14,%15," \
        "%16,%17,%18,%19,%20,%21,%22,%23,%24,%25,%26,%27,%28,%29,%30,%31}, [%32];" \
        : "=r"((r)[0]),"=r"((r)[1]),"=r"((r)[2]),"=r"((r)[3]), \
          "=r"((r)[4]),"=r"((r)[5]),"=r"((r)[6]),"=r"((r)[7]), \
          "=r"((r)[8]),"=r"((r)[9]),"=r"((r)[10]),"=r"((r)[11]), \
          "=r"((r)[12]),"=r"((r)[13]),"=r"((r)[14]),"=r"((r)[15]), \
          "=r"((r)[16]),"=r"((r)[17]),"=r"((r)[18]),"=r"((r)[19]), \
          "=r"((r)[20]),"=r"((r)[21]),"=r"((r)[22]),"=r"((r)[23]), \
          "=r"((r)[24]),"=r"((r)[25]),"=r"((r)[26]),"=r"((r)[27]), \
          "=r"((r)[28]),"=r"((r)[29]),"=r"((r)[30]),"=r"((r)[31]) \
        : "r"(tm))

// SMEM descriptor: SW128, version=1, SBO=64, LBO=1
__device__ __forceinline__ uint64_t mk_desc(uint32_t base) {
    const uint64_t B =
        (uint64_t(2) << 61) | (uint64_t(1) << 46) | (uint64_t(64) << 32) | (uint64_t(1) << 16);
    return B | ((uint64_t)(base >> 4) & 0x3FFF);
}

__device__ __forceinline__ void mma_ss(uint32_t d, uint64_t a, uint64_t b,
                                       uint32_t idesc, uint32_t acc) {
    asm volatile(
        "{\n\t.reg .pred p;\n\tsetp.ne.u32 p, %4, 0;\n\t"
        "tcgen05.mma.cta_group::1.kind::f16 [%0], %1, %2, %3, {%5,%5,%5,%5}, p;\n\t}"
        :: "r"(d), "l"(a), "l"(b), "r"(idesc), "r"(acc), "r"(0u) : "memory");
}
#endif  // TC_OK

// idesc: dtype=F32, atype=BF16, btype=BF16, N=128, M=128
#define IDESC_128 ((1u<<4)|(1u<<7)|(1u<<10)|((128u/8)<<17)|((128u/16)<<24))

// Blocked SW128 atom layout for a [128 rows, K cols] bf16 tile.
__device__ __forceinline__ uint32_t lay128(int r, int c) {
    uint32_t off = ((uint32_t)(c >> 6) * 16u + (uint32_t)(r >> 3)) * 1024u
                 + (uint32_t)(r & 7) * 128u + (uint32_t)(c & 63) * 2u;
    return off ^ ((off >> 3) & 0x70u);
}
__device__ __forceinline__ uint32_t doff(int s) {
    return (uint32_t)(s >> 2) * 1024u + (uint32_t)(s & 3) * 2u;
}

// pack two fp32 -> bf16x2 (a = low half / first element)
__device__ __forceinline__ uint32_t bf2(float a, float b) {
    uint32_t r;
    asm("cvt.rn.bf16x2.f32 %0, %1, %2;" : "=r"(r) : "f"(b), "f"(a));
    return r;
}
// hi/lo split of a pair
__device__ __forceinline__ void split2(float a, float b, uint32_t& hi, uint32_t& lo) {
    hi = bf2(a, b);
    float ra = __uint_as_float(hi << 16);
    float rb = __uint_as_float(hi & 0xFFFF0000u);
    lo = bf2(a - ra, b - rb);
}

// ---------------------------------------------------------------------------
// Per-channel pipelined GEMM: C[bz,512,128] = A[bz,512,K] @ W[bz,K,128]
//   (+bias)(+res)(relu). Grid = batch. 256 threads. 4 M-tiles per CTA.
// ---------------------------------------------------------------------------
template<int K, bool RELU, bool BIAS, bool RES>
__global__ void __launch_bounds__(256) gemm_tc(
    const float* __restrict__ A,
    const float* __restrict__ W,
    const float* __restrict__ bias,
    const float* __restrict__ Res,
    float* __restrict__ C)
{
    extern __shared__ char smem[];
    const int t = threadIdx.x;
    const int bz = blockIdx.x;

    const float* Ab = A + (size_t)bz * 512 * K;
    const float* Wb = W + (size_t)bz * K * 128;
    float*       Cb = C + (size_t)bz * 512 * 128;
    const float* Rb = RES ? Res + (size_t)bz * 512 * 128 : nullptr;

#if TC_OK
    constexpr int TILE = (K >= 128) ? 32768 : 16384;
    constexpr int OFF_WH  = 1024;
    constexpr int OFF_WL  = OFF_WH + TILE;
    constexpr int OFF_A0H = OFF_WL + TILE;
    constexpr int OFF_A0L = OFF_A0H + TILE;
    constexpr int OFF_A1H = OFF_A0L + TILE;
    constexpr int OFF_A1L = OFF_A1H + TILE;
    constexpr int NS = K / 16;

    const uint32_t sb = smem_u32(smem);
    const int wid = t >> 5, lid = t & 31;
    float* bias_s = (float*)(smem + 32);   // 128 floats at sb+32..sb+544

    if (wid == 0) TC_ALLOC(sb, 256);
    if (t == 0) { MBAR_INIT(sb + 8, 1); MBAR_INIT(sb + 16, 1); }
    __syncthreads();
    uint32_t tmem;
    asm volatile("ld.shared.b32 %0, [%1];" : "=r"(tmem) : "r"(sb));

    const int offAH[2] = {OFF_A0H, OFF_A1H};
    const int offAL[2] = {OFF_A0L, OFF_A1L};

    // ---- convert W once: fp32 [K,128] -> bf16 hi/lo [N=128,K] blocked ----
    #pragma unroll 2
    for (int i = t; i < (K / 2) * 32; i += 256) {
        int kp = i >> 5;
        int n4 = (i & 31) * 4;
        float4 v0 = *(const float4*)(Wb + (size_t)(2 * kp) * 128 + n4);
        float4 v1 = *(const float4*)(Wb + (size_t)(2 * kp + 1) * 128 + n4);
        const float* e0 = (const float*)&v0;
        const float* e1 = (const float*)&v1;
        #pragma unroll
        for (int j = 0; j < 4; j++) {
            uint32_t hi, lo;
            split2(e0[j], e1[j], hi, lo);
            uint32_t off = lay128(n4 + j, 2 * kp);
            *(uint32_t*)(smem + OFF_WH + off) = hi;
            *(uint32_t*)(smem + OFF_WL + off) = lo;
        }
    }
    if (BIAS && t < 128) bias_s[t] = bias[(size_t)bz * 128 + t];

    // ---- A tile conversion helper (as a lambda) ----
    auto convA = [&](int tile, int buf) {
        const float* At = Ab + (size_t)tile * 128 * K;
        const int ih = offAH[buf], il = offAL[buf];
        #pragma unroll 4
        for (int i = t; i < 128 * K / 4; i += 256) {
            int m  = i / (K / 4);
            int k4 = (i % (K / 4)) * 4;
            float4 v = *(const float4*)(At + (size_t)m * K + k4);
            uint2 hi, lo;
            split2(v.x, v.y, hi.x, lo.x);
            split2(v.z, v.w, hi.y, lo.y);
            uint32_t off = lay128(m, k4);
            *(uint2*)(smem + ih + off) = hi;
            *(uint2*)(smem + il + off) = lo;
        }
    };
    auto issueMMA = [&](int buf, uint32_t accOff, uint32_t barOff) {
        FENCE_ASYNC();
        if (elect_one()) {
            uint64_t ah = mk_desc(sb + offAH[buf]);
            uint64_t al = mk_desc(sb + offAL[buf]);
            uint64_t wh = mk_desc(sb + OFF_WH);
            uint64_t wl = mk_desc(sb + OFF_WL);
            uint32_t d = tmem + accOff;
            #pragma unroll
            for (int s = 0; s < NS; s++)
                mma_ss(d, ah + doff(s), wh + doff(s), IDESC_128, s > 0);
            #pragma unroll
            for (int s = 0; s < NS; s++)
                mma_ss(d, ah + doff(s), wl + doff(s), IDESC_128, 1);
            #pragma unroll
            for (int s = 0; s < NS; s++)
                mma_ss(d, al + doff(s), wh + doff(s), IDESC_128, 1);
            TC_COMMIT(sb + barOff);
        }
    };

    // ---- prologue: fill both pipeline slots ----
    convA(0, 0);
    __syncthreads();          // W + A0 ready
    if (wid == 0) issueMMA(0, 0, 8);
    convA(1, 1);
    __syncthreads();          // A1 ready
    if (wid == 0) issueMMA(1, 128, 16);

    int ph[2] = {0, 0};

    const int sp = wid & 3;        // TMEM subpartition
    const int ch = wid >> 2;       // column half
    const int m  = sp * 32 + lid;

    #pragma unroll
    for (int i = 0; i < 4; i++) {
        const int s = i & 1;
        mbar_wait(sb + 8 + 8 * s, ph[s]);
        ph[s] ^= 1;
        TC_FENCE_AFTER();

        // epilogue tile i
        {
            float* cp = Cb + ((size_t)i * 128 + m) * 128;
            const float* rp = RES ? (Rb + ((size_t)i * 128 + m) * 128) : nullptr;
            #pragma unroll
            for (int cb = 0; cb < 2; cb++) {
                const int c0 = ch * 64 + cb * 32;
                uint32_t r[32];
                TC_LD_X32(r, tmem + s * 128 + c0);
                TC_WAIT_LD();
                #pragma unroll
                for (int q8 = 0; q8 < 8; q8++) {
                    float4 v;
                    v.x = __uint_as_float(r[q8 * 4 + 0]);
                    v.y = __uint_as_float(r[q8 * 4 + 1]);
                    v.z = __uint_as_float(r[q8 * 4 + 2]);
                    v.w = __uint_as_float(r[q8 * 4 + 3]);
                    if (BIAS) {
                        v.x += bias_s[c0 + q8 * 4 + 0];
                        v.y += bias_s[c0 + q8 * 4 + 1];
                        v.z += bias_s[c0 + q8 * 4 + 2];
                        v.w += bias_s[c0 + q8 * 4 + 3];
                    }
                    if (RES) {
                        float4 rv = *(const float4*)(rp + c0 + q8 * 4);
                        v.x += rv.x; v.y += rv.y; v.z += rv.z; v.w += rv.w;
                    }
                    if (RELU) {
                        v.x = fmaxf(v.x, 0.f); v.y = fmaxf(v.y, 0.f);
                        v.z = fmaxf(v.z, 0.f); v.w = fmaxf(v.w, 0.f);
                    }
                    *(float4*)(cp + c0 + q8 * 4) = v;
                }
            }
            TC_FENCE_BEFORE();
        }

        if (i + 2 < 4) {
            convA(i + 2, s);
            __syncthreads();   // epilogue LDTMs + A writes done in all warps
            if (wid == 0) issueMMA(s, (uint32_t)s * 128, 8 + 8 * (uint32_t)s);
        }
    }

    __syncthreads();
    if (t == 0) { MBAR_INVAL(sb + 8); MBAR_INVAL(sb + 16); }
    __syncthreads();
    if (wid == 0) TC_DEALLOC(tmem, 256);

#else
    // ================== FFMA fallback (base sm_103 pass) ==================
    float (*As)[132] = (float(*)[132])(smem + 1024);
    float (*Ws)[128] = (float(*)[128])(smem + 1024 + 16 * 132 * 4);
    const int tx = t & 15;
    const int ty = t >> 4;

    for (int mt = 0; mt < 4; mt++) {
        const float* Abt = Ab + (size_t)mt * 128 * K;
        float*       Cbt = Cb + (size_t)mt * 128 * 128;
        const float* Rbt = RES ? (Rb + (size_t)mt * 128 * 128) : nullptr;

        float acc[8][8];
        #pragma unroll
        for (int i = 0; i < 8; i++)
            #pragma unroll
            for (int j = 0; j < 8; j++) acc[i][j] = 0.f;

        for (int k0 = 0; k0 < K; k0 += 16) {
            {
                int r = t >> 1;
                int c = (t & 1) * 8;
                const float* src = Abt + (size_t)r * K + k0 + c;
                float4 v0 = *(const float4*)(src);
                float4 v1 = *(const float4*)(src + 4);
                As[c + 0][r] = v0.x; As[c + 1][r] = v0.y;
                As[c + 2][r] = v0.z; As[c + 3][r] = v0.w;
                As[c + 4][r] = v1.x; As[c + 5][r] = v1.y;
                As[c + 6][r] = v1.z; As[c + 7][r] = v1.w;
            }
            {
                const float4* src = (const float4*)(Wb + (size_t)k0 * 128);
                float4* dst = (float4*)(&Ws[0][0]);
                dst[t]       = src[t];
                dst[t + 256] = src[t + 256];
            }
            __syncthreads();
            #pragma unroll
            for (int k = 0; k < 16; k++) {
                float a[8], w[8];
                *(float4*)(a)     = *(const float4*)&As[k][ty * 8];
                *(float4*)(a + 4) = *(const float4*)&As[k][ty * 8 + 4];
                *(float4*)(w)     = *(const float4*)&Ws[k][tx * 8];
                *(float4*)(w + 4) = *(const float4*)&Ws[k][tx * 8 + 4];
                #pragma unroll
                for (int i = 0; i < 8; i++)
                    #pragma unroll
                    for (int j = 0; j < 8; j++)
                        acc[i][j] += a[i] * w[j];
            }
            __syncthreads();
        }

        float bcol[8];
        if (BIAS) {
            #pragma unroll
            for (int j = 0; j < 8; j++)
                bcol[j] = bias[(size_t)bz * 128 + tx * 8 + j];
        }
        #pragma unroll
        for (int i = 0; i < 8; i++) {
            int row = ty * 8 + i;
            float* cp = Cbt + (size_t)row * 128 + tx * 8;
            float rr[8];
            if (RES) {
                float4 r0 = *(const float4*)(Rbt + (size_t)row * 128 + tx * 8);
                float4 r1 = *(const float4*)(Rbt + (size_t)row * 128 + tx * 8 + 4);
                rr[0]=r0.x; rr[1]=r0.y; rr[2]=r0.z; rr[3]=r0.w;
                rr[4]=r1.x; rr[5]=r1.y; rr[6]=r1.z; rr[7]=r1.w;
            }
            float o[8];
            #pragma unroll
            for (int j = 0; j < 8; j++) {
                float v = acc[i][j];
                if (BIAS) v += bcol[j];
                if (RES)  v += rr[j];
                if (RELU) v = fmaxf(v, 0.f);
                o[j] = v;
            }
            *(float4*)(cp)     = make_float4(o[0], o[1], o[2], o[3]);
            *(float4*)(cp + 4) = make_float4(o[4], o[5], o[6], o[7]);
        }
        __syncthreads();
    }
#endif
}

// ---------------------------------------------------------------------------
// Attention core: 256 threads handle 2 batches (float4 staging).
// ---------------------------------------------------------------------------
__global__ void __launch_bounds__(256) attn_kernel(
    const float* __restrict__ Q, const float* __restrict__ Kk,
    const float* __restrict__ V, float* __restrict__ T)
{
    const int blk = blockIdx.x;       // 0 .. 64*256-1
    const int ef  = blk >> 8;
    const int bp  = (blk & 255) << 1;

    __shared__ float qs[2][NO][132];
    __shared__ float ks[2][NO][132];
    __shared__ float vs[2][NO][132];
    __shared__ float lg[2][4][NO][12];

    const int t  = threadIdx.x;
    const int g  = t >> 7;
    const int tl = t & 127;
    const int b  = bp + g;

    for (int idx = tl; idx < NO * 32; idx += 128) {
        int o  = idx >> 5;
        int c4 = (idx & 31) * 4;
        size_t ga = ((size_t)(ef * NO + o) * NB + b) * 128 + c4;
        *(float4*)&qs[g][o][c4] = *(const float4*)(Q + ga);
        *(float4*)&ks[g][o][c4] = *(const float4*)(Kk + ga);
        *(float4*)&vs[g][o][c4] = *(const float4*)(V + ga);
    }
    __syncthreads();

    const float scale = 0.17677669529663687f;
    for (int e = tl; e < 4 * NO * NO; e += 128) {
        int h   = e / (NO * NO);
        int rem = e - h * NO * NO;
        int i   = rem / NO;
        int j   = rem - i * NO;
        float s = 0.f;
        #pragma unroll
        for (int d = 0; d < 32; d++) s += qs[g][i][h * 32 + d] * ks[g][j][h * 32 + d];
        lg[g][h][i][j] = s * scale;
    }
    __syncthreads();

    if (tl < 4 * NO) {
        int h = tl / NO, i = tl - (tl / NO) * NO;
        float mx = -1e30f;
        #pragma unroll
        for (int j = 0; j < NO; j++) mx = fmaxf(mx, lg[g][h][i][j]);
        float ex[NO]; float s = 0.f;
        #pragma unroll
        for (int j = 0; j < NO; j++) { ex[j] = __expf(lg[g][h][i][j] - mx); s += ex[j]; }
        float inv = 1.f / s;
        #pragma unroll
        for (int j = 0; j < NO; j++) lg[g][h][i][j] = ex[j] * inv;
    }
    __syncthreads();

    const int c = tl, h = c >> 5;
    #pragma unroll
    for (int i = 0; i < NO; i++) {
        float s = 0.f;
        #pragma unroll
        for (int j = 0; j < NO; j++) s += lg[g][h][i][j] * vs[g][j][c];
        T[((size_t)(ef * NO + i) * NB + b) * 128 + c] = s;
    }
}

__global__ void __launch_bounds__(256) pool_kernel(
    const float* __restrict__ Hin, float* __restrict__ P)
{
    int idx = blockIdx.x * 256 + threadIdx.x;
    if (idx >= NEF * NB * NDH) return;
    int c = idx & 127, b = (idx >> 7) & 511, ef = idx >> 16;
    float s = 0.f;
    #pragma unroll
    for (int o = 0; o < NO; o++)
        s += Hin[((size_t)(ef * NO + o) * NB + b) * 128 + c];
    P[idx] = s * (1.f / 9.f);
}

__global__ void __launch_bounds__(256) final_kernel(
    const float* __restrict__ A, const float* __restrict__ W,
    const float* __restrict__ bias, float* __restrict__ Out)
{
    const int mt = blockIdx.x;
    const int ef = blockIdx.y;
    __shared__ float As[32][128];
    __shared__ float Ws[128][NFINAL];
    __shared__ float bs[NFINAL];
    const int t = threadIdx.x;
    const float* Ab = A + ((size_t)ef * NB + mt * 32) * 128;
    for (int i = t; i < 32 * 128 / 4; i += 256)
        ((float4*)&As[0][0])[i] = ((const float4*)Ab)[i];
    for (int i = t; i < 128 * NFINAL; i += 256)
        Ws[i / NFINAL][i % NFINAL] = W[(size_t)ef * 128 * NFINAL + i];
    if (t < NFINAL) bs[t] = bias[ef * NFINAL + t];
    __syncthreads();
    for (int idx = t; idx < 32 * NFINAL; idx += 256) {
        int r = idx / NFINAL, j = idx - r * NFINAL;
        float s = bs[j];
        #pragma unroll 16
        for (int k = 0; k < 128; k++) s += As[r][k] * Ws[k][j];
        Out[((size_t)ef * NB + mt * 32 + r) * NFINAL + j] = s;
    }
}

// ---------------------------------------------------------------------------
extern "C" void kernel_launch(void* const* d_in, const int* in_sizes, int n_in,
                              void* d_out, int out_size)
{
    const float* x   = (const float*)d_in[0];
    const float* fw1 = (const float*)d_in[1];
    const float* fb1 = (const float*)d_in[2];
    const float* fw2 = (const float*)d_in[3];
    const float* fb2 = (const float*)d_in[4];
    const float* aw[2][5];
    const float* apb[2];
    for (int i = 0; i < 2; i++) {
        for (int n = 0; n < 5; n++) aw[i][n] = (const float*)d_in[5 + i * 6 + n];
        apb[i] = (const float*)d_in[5 + i * 6 + 5];
    }
    const float* pw1 = (const float*)d_in[17];
    const float* pb1 = (const float*)d_in[18];
    const float* pw2 = (const float*)d_in[19];
    const float* pb2 = (const float*)d_in[20];
    float* out = (float*)d_out;

    float *H1, *H2, *Q, *K, *V, *T, *PO, *P;
    cudaGetSymbolAddress((void**)&H1, g_h1);
    cudaGetSymbolAddress((void**)&H2, g_h2);
    cudaGetSymbolAddress((void**)&Q,  g_q);
    cudaGetSymbolAddress((void**)&K,  g_k);
    cudaGetSymbolAddress((void**)&V,  g_v);
    cudaGetSymbolAddress((void**)&T,  g_t);
    cudaGetSymbolAddress((void**)&PO, g_po);
    cudaGetSymbolAddress((void**)&P,  g_p);

    const int SM32  = 1024 + 6 * 16384;   // 99,328
    const int SM128 = 1024 + 6 * 32768;   // 197,632
    cudaFuncSetAttribute(gemm_tc<32,  true,  true,  false>,
                         cudaFuncAttributeMaxDynamicSharedMemorySize, SM32);
    cudaFuncSetAttribute(gemm_tc<128, true,  true,  false>,
                         cudaFuncAttributeMaxDynamicSharedMemorySize, SM128);
    cudaFuncSetAttribute(gemm_tc<128, false, false, false>,
                         cudaFuncAttributeMaxDynamicSharedMemorySize, SM128);
    cudaFuncSetAttribute(gemm_tc<128, false, false, true>,
                         cudaFuncAttributeMaxDynamicSharedMemorySize, SM128);

    // feature_fc
    gemm_tc<32,  true, true, false><<<NCH, 256, SM32 >>>(x,  fw1, fb1, nullptr, H1);
    gemm_tc<128, true, true, false><<<NCH, 256, SM128>>>(H1, fw2, fb2, nullptr, H2);

    // two ChannelMHA blocks
    const float* X = H2;
    float* Y = H1;
    for (int a = 0; a < 2; a++) {
        gemm_tc<128, false, false, false><<<NCH, 256, SM128>>>(X, aw[a][0], nullptr, nullptr, Q);
        gemm_tc<128, false, false, false><<<NCH, 256, SM128>>>(X, aw[a][1], nullptr, nullptr, K);
        gemm_tc<128, false, false, false><<<NCH, 256, SM128>>>(X, aw[a][2], nullptr, nullptr, V);
        attn_kernel<<<NEF * NB / 2, 256>>>(Q, K, V, T);
        gemm_tc<128, false, false, true ><<<NCH, 256, SM128>>>(T, aw[a][3], nullptr, X, Q);
        gemm_tc<128, true,  true,  false><<<NCH, 256, SM128>>>(Q, aw[a][4], apb[a], nullptr, Y);
        const float* nX = Y;
        Y = (a == 0) ? H2 : H1;
        X = nX;
    }

    pool_kernel<<<(NEF * NB * NDH + 255) / 256, 256>>>(X, PO);
    gemm_tc<128, true, true, false><<<NEF, 256, SM128>>>(PO, pw1, pb1, nullptr, P);
    final_kernel<<<dim3(16, NEF), 256>>>(P, pw2, pb2, out);
}